// round 9
// baseline (speedup 1.0000x reference)
#include <cuda_runtime.h>
#include <cuda_fp16.h>
#include <cstdint>

#define MAX_LOCAL 55000
#define MAX_EDGES 800000
#define C1 128
#define C2 64

// ---- static scratch (allocation-free) ----
__device__ __half g_xd [MAX_LOCAL * C1];     // fp16 (X * deg)
__device__ __half g_agg[MAX_LOCAL * C1];     // gathered sums (owned rows)
__device__ __half g_h2 [MAX_LOCAL * C2];     // (x2 @ W2) * deg (owned rows)
__device__ int    g_rowstart[MAX_LOCAL + 1];
__device__ int    g_cursor  [MAX_LOCAL];
__device__ int    g_csrcol  [MAX_EDGES];
// meta: [0,MAX_LOCAL) hist | +64 flags | +64 agg | +64 pfx
__device__ int    g_meta[MAX_LOCAL + 192];

// ===========================================================================
// Xd = fp16(X * deg)  (streaming, 8 halfs/thread)
// ===========================================================================
__global__ __launch_bounds__(256) void conv_deg(
    const float* __restrict__ X, const float* __restrict__ deg,
    __half* __restrict__ Xd, int n8)
{
    const int i = blockIdx.x * blockDim.x + threadIdx.x;
    if (i >= n8) return;
    const int row = i >> 4;                 // 16 groups of 8 per 128-ch row
    const float d = __ldg(deg + row);
    const float4 v0 = ((const float4*)X)[i * 2];
    const float4 v1 = ((const float4*)X)[i * 2 + 1];
    __half2 h0 = __floats2half2_rn(v0.x * d, v0.y * d);
    __half2 h1 = __floats2half2_rn(v0.z * d, v0.w * d);
    __half2 h2 = __floats2half2_rn(v1.x * d, v1.y * d);
    __half2 h3 = __floats2half2_rn(v1.z * d, v1.w * d);
    uint4 u;
    u.x = *(unsigned*)&h0; u.y = *(unsigned*)&h1;
    u.z = *(unsigned*)&h2; u.w = *(unsigned*)&h3;
    ((uint4*)Xd)[i] = u;
}

// ===========================================================================
// CSR build (edges with er >= owned are dropped: never consumed)
// ===========================================================================
__global__ __launch_bounds__(256) void edge_hist(
    const int* __restrict__ er, int* __restrict__ cnt, int nE, int owned)
{
    int e = blockIdx.x * blockDim.x + threadIdx.x;
    if (e < nE) {
        int r = er[e];
        if (r < owned) atomicAdd(&cnt[r], 1);
    }
}

__global__ __launch_bounds__(1024) void scan_csr(
    const int* __restrict__ cnt, int* __restrict__ rs, int* __restrict__ cur,
    int* flags, int* agg, int* pfx, int n)
{
    __shared__ int wsum[32];
    __shared__ int s_excl;
    const int b = blockIdx.x, t = threadIdx.x;
    const int i = b * 1024 + t;
    const int lane = t & 31, wid = t >> 5;

    int v = (i < n) ? cnt[i] : 0;
    int incl = v;
#pragma unroll
    for (int o = 1; o < 32; o <<= 1) {
        int u = __shfl_up_sync(~0u, incl, o);
        if (lane >= o) incl += u;
    }
    if (lane == 31) wsum[wid] = incl;
    __syncthreads();
    if (wid == 0) {
        int ws = wsum[lane];
#pragma unroll
        for (int o = 1; o < 32; o <<= 1) {
            int u = __shfl_up_sync(~0u, ws, o);
            if (lane >= o) ws += u;
        }
        wsum[lane] = ws;
    }
    __syncthreads();
    const int blockIncl = incl + (wid ? wsum[wid - 1] : 0);
    const int total = wsum[31];

    if (t == 0) {
        agg[b] = total;
        __threadfence();
        ((volatile int*)flags)[b] = 1;
        int ex = 0;
        for (int p = b - 1; p >= 0; --p) {
            int f;
            do { f = ((volatile int*)flags)[p]; } while (f == 0);
            __threadfence();
            if (f == 2) { ex += pfx[p]; break; }
            ex += agg[p];
        }
        pfx[b] = ex + total;
        __threadfence();
        ((volatile int*)flags)[b] = 2;
        s_excl = ex;
    }
    __syncthreads();
    if (i < n) {
        const int base = s_excl + blockIncl - v;
        rs[i]  = base;
        cur[i] = base;
        if (i == n - 1) rs[n] = base + v;
    }
}

__global__ __launch_bounds__(256) void csr_fill(
    const int* __restrict__ er, const int* __restrict__ ec,
    int* __restrict__ cursor, int* __restrict__ col, int nE, int owned)
{
    int e = blockIdx.x * blockDim.x + threadIdx.x;
    if (e < nE) {
        int r = er[e];
        if (r < owned) {
            int p = atomicAdd(&cursor[r], 1);
            col[p] = ec[e];
        }
    }
}

// ===========================================================================
// Gather (layer 1, pre-GEMM): agg[row,:] = fp16( sum_j Xd[col_j,:] )
// warp/row, 4-edge unroll, uint2 (4 halfs) per lane, fp32 accum
// ===========================================================================
__global__ __launch_bounds__(256) void gather_agg(
    const __half* __restrict__ Xd, const int* __restrict__ rs,
    const int* __restrict__ cols, __half* __restrict__ AGG, int owned)
{
    const int row  = (blockIdx.x * 256 + threadIdx.x) >> 5;
    const int lane = threadIdx.x & 31;
    if (row >= owned) return;
    const int s = __ldg(rs + row);
    const int e = __ldg(rs + row + 1);

    float a0 = 0.f, a1 = 0.f, a2 = 0.f, a3 = 0.f;
    int j = s;
    for (; j + 3 < e; j += 4) {
        int c0 = __ldg(cols + j),     c1 = __ldg(cols + j + 1);
        int c2 = __ldg(cols + j + 2), c3 = __ldg(cols + j + 3);
        const uint2 u0 = *(const uint2*)(Xd + (size_t)c0 * C1 + lane * 4);
        const uint2 u1 = *(const uint2*)(Xd + (size_t)c1 * C1 + lane * 4);
        const uint2 u2 = *(const uint2*)(Xd + (size_t)c2 * C1 + lane * 4);
        const uint2 u3 = *(const uint2*)(Xd + (size_t)c3 * C1 + lane * 4);
        float2 f;
        f = __half22float2(*(const __half2*)&u0.x); a0 += f.x; a1 += f.y;
        f = __half22float2(*(const __half2*)&u0.y); a2 += f.x; a3 += f.y;
        f = __half22float2(*(const __half2*)&u1.x); a0 += f.x; a1 += f.y;
        f = __half22float2(*(const __half2*)&u1.y); a2 += f.x; a3 += f.y;
        f = __half22float2(*(const __half2*)&u2.x); a0 += f.x; a1 += f.y;
        f = __half22float2(*(const __half2*)&u2.y); a2 += f.x; a3 += f.y;
        f = __half22float2(*(const __half2*)&u3.x); a0 += f.x; a1 += f.y;
        f = __half22float2(*(const __half2*)&u3.y); a2 += f.x; a3 += f.y;
    }
    for (; j < e; ++j) {
        const int c0 = __ldg(cols + j);
        const uint2 u0 = *(const uint2*)(Xd + (size_t)c0 * C1 + lane * 4);
        float2 f;
        f = __half22float2(*(const __half2*)&u0.x); a0 += f.x; a1 += f.y;
        f = __half22float2(*(const __half2*)&u0.y); a2 += f.x; a3 += f.y;
    }
    __half2 o0 = __floats2half2_rn(a0, a1);
    __half2 o1 = __floats2half2_rn(a2, a3);
    uint2 u;
    u.x = *(unsigned*)&o0; u.y = *(unsigned*)&o1;
    *(uint2*)(AGG + (size_t)row * C1 + lane * 4) = u;
}

// ===========================================================================
// Fused double GEMM:
//   x2 = relu( (agg @ W1) * deg + b1 )          [smem-resident tile]
//   h2 = fp16( (x2 @ W2) * deg )                [global]
// Block: 256 thr = 8 warps (4m x 2n). BM=128. K=128 both stages.
// smem 48KB: [0,32K) A / x2 tile (128 rows x 256B, swizzled)
//            [32K,48K) W chunk (stage1: 64k x 128n; stage2: 128k x 64n)
// ===========================================================================
__device__ __forceinline__ void ldsm4(unsigned& r0, unsigned& r1,
                                      unsigned& r2, unsigned& r3, unsigned a) {
    asm volatile("ldmatrix.sync.aligned.m8n8.x4.shared.b16 {%0,%1,%2,%3}, [%4];"
                 : "=r"(r0), "=r"(r1), "=r"(r2), "=r"(r3) : "r"(a));
}
__device__ __forceinline__ void ldsm4t(unsigned& r0, unsigned& r1,
                                       unsigned& r2, unsigned& r3, unsigned a) {
    asm volatile("ldmatrix.sync.aligned.m8n8.x4.trans.shared.b16 {%0,%1,%2,%3}, [%4];"
                 : "=r"(r0), "=r"(r1), "=r"(r2), "=r"(r3) : "r"(a));
}
__device__ __forceinline__ void mma16816(float& c0, float& c1, float& c2, float& c3,
                                         unsigned a0, unsigned a1, unsigned a2, unsigned a3,
                                         unsigned b0, unsigned b1) {
    asm volatile("mma.sync.aligned.m16n8k16.row.col.f32.f16.f16.f32 "
                 "{%0,%1,%2,%3}, {%4,%5,%6,%7}, {%8,%9}, {%0,%1,%2,%3};"
                 : "+f"(c0), "+f"(c1), "+f"(c2), "+f"(c3)
                 : "r"(a0), "r"(a1), "r"(a2), "r"(a3), "r"(b0), "r"(b1));
}
__device__ __forceinline__ void cpa16(unsigned dst, const void* src, bool p) {
    int sz = p ? 16 : 0;
    asm volatile("cp.async.cg.shared.global [%0], [%1], 16, %2;"
                 :: "r"(dst), "l"(src), "r"(sz));
}

__global__ __launch_bounds__(256) void gemm_fused(
    const __half* __restrict__ AGG, const float* __restrict__ W1,
    const float* __restrict__ B1f, const float* __restrict__ W2,
    const float* __restrict__ deg, __half* __restrict__ H2, int owned)
{
    __shared__ __align__(16) char smem[49152];
    const unsigned sbase = (unsigned)__cvta_generic_to_shared(smem);
    const unsigned wB    = sbase + 32768;

    const int t     = threadIdx.x;
    const int warp  = t >> 5;
    const int lane  = t & 31;
    const int warpM = warp >> 1;
    const int warpN = warp & 1;
    const int rbase = blockIdx.x * 128;
    const int hi    = lane >> 4;

    int rA[2], rA7[2];
#pragma unroll
    for (int mt = 0; mt < 2; ++mt) {
        rA[mt]  = warpM * 32 + mt * 16 + (lane & 15);
        rA7[mt] = rA[mt] & 7;
    }

    // ---- A tile via cp.async (128 rows x 256B, 16 chunks/row, swizzled) ----
    {
        const int c = t & 15, rr0 = t >> 4;
#pragma unroll
        for (int p = 0; p < 8; ++p) {
            const int rr = p * 16 + rr0;
            const int gr = rbase + rr;
            const unsigned dst = sbase + rr * 256 + ((c ^ (rr & 7)) << 4);
            cpa16(dst, AGG + (size_t)gr * C1 + c * 8, gr < owned);
        }
    }
    asm volatile("cp.async.commit_group;");

    // ---- W1 chunk loader: 64 k-rows x 128 cols fp32 -> fp16 swizzled ----
    auto load_w1 = [&](int h) {
        const int c = t & 15, kr0 = t >> 4;
#pragma unroll
        for (int p = 0; p < 4; ++p) {
            const int kr = p * 16 + kr0;
            const float* src = W1 + (size_t)(h * 64 + kr) * C1 + c * 8;
            const float4 va = *(const float4*)src;
            const float4 vb = *(const float4*)(src + 4);
            __half2 h0 = __floats2half2_rn(va.x, va.y);
            __half2 h1 = __floats2half2_rn(va.z, va.w);
            __half2 h2 = __floats2half2_rn(vb.x, vb.y);
            __half2 h3 = __floats2half2_rn(vb.z, vb.w);
            uint4 u;
            u.x = *(unsigned*)&h0; u.y = *(unsigned*)&h1;
            u.z = *(unsigned*)&h2; u.w = *(unsigned*)&h3;
            *(uint4*)(smem + 32768 + kr * 256 + ((c ^ (kr & 7)) << 4)) = u;
        }
    };

    float acc[2][8][4];
#pragma unroll
    for (int mt = 0; mt < 2; ++mt)
#pragma unroll
        for (int nt = 0; nt < 8; ++nt)
#pragma unroll
            for (int c = 0; c < 4; ++c) acc[mt][nt][c] = 0.f;

    auto compute_s1 = [&](int h) {
#pragma unroll
        for (int step = 0; step < 4; ++step) {
            const int kkA = h * 4 + step;
            unsigned a[2][4], bq[4][4];
#pragma unroll
            for (int mt = 0; mt < 2; ++mt) {
                const unsigned addr = sbase + rA[mt] * 256 +
                                      (((kkA * 2 + hi) ^ rA7[mt]) << 4);
                ldsm4(a[mt][0], a[mt][1], a[mt][2], a[mt][3], addr);
            }
            const int kr = step * 16 + (lane & 15);
#pragma unroll
            for (int g = 0; g < 4; ++g) {
                const int nch = warpN * 8 + g * 2 + hi;
                const unsigned addr = wB + kr * 256 + ((nch ^ (kr & 7)) << 4);
                ldsm4t(bq[g][0], bq[g][1], bq[g][2], bq[g][3], addr);
            }
#pragma unroll
            for (int mt = 0; mt < 2; ++mt)
#pragma unroll
                for (int nt = 0; nt < 8; ++nt)
                    mma16816(acc[mt][nt][0], acc[mt][nt][1],
                             acc[mt][nt][2], acc[mt][nt][3],
                             a[mt][0], a[mt][1], a[mt][2], a[mt][3],
                             bq[nt >> 1][(nt & 1) * 2], bq[nt >> 1][(nt & 1) * 2 + 1]);
        }
    };

    load_w1(0);
    asm volatile("cp.async.wait_group 0;");
    __syncthreads();
    compute_s1(0);
    __syncthreads();
    load_w1(1);
    __syncthreads();
    compute_s1(1);
    __syncthreads();              // A-tile reads complete; safe to overwrite

    // ---- epilogue1: x2 = relu(acc*deg + b1) -> fp16 into A region ----
    const int g2 = lane >> 2, tq = lane & 3;
#pragma unroll
    for (int mt = 0; mt < 2; ++mt) {
        const int lr0 = warpM * 32 + mt * 16 + g2;
        const int lr1 = lr0 + 8;
        const int gr0 = rbase + lr0, gr1 = rbase + lr1;
        const float d0 = (gr0 < owned) ? __ldg(deg + gr0) : 0.f;
        const float d1 = (gr1 < owned) ? __ldg(deg + gr1) : 0.f;
#pragma unroll
        for (int nt = 0; nt < 8; ++nt) {
            const int cc = warpN * 64 + nt * 8 + tq * 2;
            const float2 bb = *(const float2*)(B1f + cc);
            __half2 v0 = __floats2half2_rn(
                fmaxf(fmaf(acc[mt][nt][0], d0, bb.x), 0.f),
                fmaxf(fmaf(acc[mt][nt][1], d0, bb.y), 0.f));
            __half2 v1 = __floats2half2_rn(
                fmaxf(fmaf(acc[mt][nt][2], d1, bb.x), 0.f),
                fmaxf(fmaf(acc[mt][nt][3], d1, bb.y), 0.f));
            *(__half2*)(smem + lr0 * 256 + (((cc >> 3) ^ (lr0 & 7)) << 4) + (cc & 7) * 2) = v0;
            *(__half2*)(smem + lr1 * 256 + (((cc >> 3) ^ (lr1 & 7)) << 4) + (cc & 7) * 2) = v1;
        }
    }

    // ---- load W2: 128 k-rows x 64 cols -> fp16 swizzled (row = 128B) ----
    {
        const int c = t & 7, kr0 = t >> 3;
#pragma unroll
        for (int p = 0; p < 4; ++p) {
            const int kr = p * 32 + kr0;
            const float* src = W2 + (size_t)kr * C2 + c * 8;
            const float4 va = *(const float4*)src;
            const float4 vb = *(const float4*)(src + 4);
            __half2 h0 = __floats2half2_rn(va.x, va.y);
            __half2 h1 = __floats2half2_rn(va.z, va.w);
            __half2 h2 = __floats2half2_rn(vb.x, vb.y);
            __half2 h3 = __floats2half2_rn(vb.z, vb.w);
            uint4 u;
            u.x = *(unsigned*)&h0; u.y = *(unsigned*)&h1;
            u.z = *(unsigned*)&h2; u.w = *(unsigned*)&h3;
            *(uint4*)(smem + 32768 + kr * 128 + ((c ^ (kr & 7)) << 4)) = u;
        }
    }
    __syncthreads();

    // ---- stage 2: h2 = (x2 @ W2) * deg ----
    float acc2[2][4][4];
#pragma unroll
    for (int mt = 0; mt < 2; ++mt)
#pragma unroll
        for (int nt = 0; nt < 4; ++nt)
#pragma unroll
            for (int c = 0; c < 4; ++c) acc2[mt][nt][c] = 0.f;

#pragma unroll
    for (int step = 0; step < 8; ++step) {
        unsigned a[2][4], bq[2][4];
#pragma unroll
        for (int mt = 0; mt < 2; ++mt) {
            const unsigned addr = sbase + rA[mt] * 256 +
                                  (((step * 2 + hi) ^ rA7[mt]) << 4);
            ldsm4(a[mt][0], a[mt][1], a[mt][2], a[mt][3], addr);
        }
        const int kr = step * 16 + (lane & 15);
#pragma unroll
        for (int g = 0; g < 2; ++g) {
            const int nch = warpN * 4 + g * 2 + hi;
            const unsigned addr = wB + kr * 128 + ((nch ^ (kr & 7)) << 4);
            ldsm4t(bq[g][0], bq[g][1], bq[g][2], bq[g][3], addr);
        }
#pragma unroll
        for (int mt = 0; mt < 2; ++mt)
#pragma unroll
            for (int nt = 0; nt < 4; ++nt)
                mma16816(acc2[mt][nt][0], acc2[mt][nt][1],
                         acc2[mt][nt][2], acc2[mt][nt][3],
                         a[mt][0], a[mt][1], a[mt][2], a[mt][3],
                         bq[nt >> 1][(nt & 1) * 2], bq[nt >> 1][(nt & 1) * 2 + 1]);
    }

    // ---- epilogue2: store h2 fp16 ----
#pragma unroll
    for (int mt = 0; mt < 2; ++mt) {
        const int gr0 = rbase + warpM * 32 + mt * 16 + g2;
        const int gr1 = gr0 + 8;
        const float d0 = (gr0 < owned) ? __ldg(deg + gr0) : 0.f;
        const float d1 = (gr1 < owned) ? __ldg(deg + gr1) : 0.f;
#pragma unroll
        for (int nt = 0; nt < 4; ++nt) {
            const int cc = warpN * 32 + nt * 8 + tq * 2;
            if (gr0 < owned) {
                __half2 h = __floats2half2_rn(acc2[mt][nt][0] * d0, acc2[mt][nt][1] * d0);
                *(__half2*)(H2 + (size_t)gr0 * C2 + cc) = h;
            }
            if (gr1 < owned) {
                __half2 h = __floats2half2_rn(acc2[mt][nt][2] * d1, acc2[mt][nt][3] * d1);
                *(__half2*)(H2 + (size_t)gr1 * C2 + cc) = h;
            }
        }
    }
}

// ===========================================================================
// Gather 2: out[row,:] = (sum_{col_j<owned} h2[col_j,:]) * deg[row] + b2
// ===========================================================================
__global__ __launch_bounds__(256) void gather_out(
    const __half* __restrict__ H, const int* __restrict__ rs,
    const int* __restrict__ cols, const float* __restrict__ deg,
    const float* __restrict__ b, float* __restrict__ out, int owned)
{
    const int row  = (blockIdx.x * 256 + threadIdx.x) >> 5;
    const int lane = threadIdx.x & 31;
    if (row >= owned) return;
    const int s = __ldg(rs + row);
    const int e = __ldg(rs + row + 1);

    float a0 = 0.f, a1 = 0.f, b0 = 0.f, b1 = 0.f;
    int j = s;
    for (; j + 3 < e; j += 4) {
        int c0 = __ldg(cols + j),     c1 = __ldg(cols + j + 1);
        int c2 = __ldg(cols + j + 2), c3 = __ldg(cols + j + 3);
        if (c0 < owned) {
            float2 f = __half22float2(*(const __half2*)(H + (size_t)c0 * C2 + lane * 2));
            a0 += f.x; a1 += f.y;
        }
        if (c1 < owned) {
            float2 f = __half22float2(*(const __half2*)(H + (size_t)c1 * C2 + lane * 2));
            b0 += f.x; b1 += f.y;
        }
        if (c2 < owned) {
            float2 f = __half22float2(*(const __half2*)(H + (size_t)c2 * C2 + lane * 2));
            a0 += f.x; a1 += f.y;
        }
        if (c3 < owned) {
            float2 f = __half22float2(*(const __half2*)(H + (size_t)c3 * C2 + lane * 2));
            b0 += f.x; b1 += f.y;
        }
    }
    for (; j < e; ++j) {
        const int c0 = __ldg(cols + j);
        if (c0 < owned) {
            float2 f = __half22float2(*(const __half2*)(H + (size_t)c0 * C2 + lane * 2));
            a0 += f.x; a1 += f.y;
        }
    }
    const float d = __ldg(deg + row);
    const float2 bb = ((const float2*)b)[lane];
    float2 o;
    o.x = fmaf(a0 + b0, d, bb.x);
    o.y = fmaf(a1 + b1, d, bb.y);
    *(float2*)(out + (size_t)row * C2 + lane * 2) = o;
}

// ===========================================================================
extern "C" void kernel_launch(void* const* d_in, const int* in_sizes, int n_in,
                              void* d_out, int out_size)
{
    const float* x   = (const float*)d_in[0];
    const float* deg = (const float*)d_in[1];
    const float* w1  = (const float*)d_in[2];
    const float* b1  = (const float*)d_in[3];
    const float* w2  = (const float*)d_in[4];
    const float* b2  = (const float*)d_in[5];
    const int*   er  = (const int*)d_in[6];
    const int*   ec  = (const int*)d_in[7];

    const int nloc  = in_sizes[0] / C1;     // 55000
    const int nE    = in_sizes[6];          // 800000
    const int owned = out_size / C2;        // 50000
    float* out = (float*)d_out;

    __half *p_xd, *p_agg, *p_h2;
    int *p_rs, *p_cur, *p_col, *p_meta;
    cudaGetSymbolAddress((void**)&p_xd,   g_xd);
    cudaGetSymbolAddress((void**)&p_agg,  g_agg);
    cudaGetSymbolAddress((void**)&p_h2,   g_h2);
    cudaGetSymbolAddress((void**)&p_rs,   g_rowstart);
    cudaGetSymbolAddress((void**)&p_cur,  g_cursor);
    cudaGetSymbolAddress((void**)&p_col,  g_csrcol);
    cudaGetSymbolAddress((void**)&p_meta, g_meta);

    int* p_hist  = p_meta;
    int* p_flags = p_meta + MAX_LOCAL;
    int* p_agg2  = p_meta + MAX_LOCAL + 64;
    int* p_pfx   = p_meta + MAX_LOCAL + 128;

    static cudaStream_t s2 = nullptr;
    static cudaEvent_t evFork = nullptr, evJoin = nullptr;
    if (s2 == nullptr) {
        cudaStreamCreateWithFlags(&s2, cudaStreamNonBlocking);
        cudaEventCreateWithFlags(&evFork, cudaEventDisableTiming);
        cudaEventCreateWithFlags(&evJoin, cudaEventDisableTiming);
    }

    // ---- fork: CSR on s2, concurrent with conv_deg on stream 0 ----
    cudaEventRecord(evFork, 0);
    cudaStreamWaitEvent(s2, evFork, 0);

    cudaMemsetAsync(p_meta, 0, (size_t)(MAX_LOCAL + 64) * sizeof(int), s2);
    edge_hist<<<(nE + 255) / 256, 256, 0, s2>>>(er, p_hist, nE, owned);
    const int nB = (owned + 1023) / 1024;
    scan_csr<<<nB, 1024, 0, s2>>>(p_hist, p_rs, p_cur, p_flags, p_agg2, p_pfx, owned);
    csr_fill<<<(nE + 255) / 256, 256, 0, s2>>>(er, ec, p_cur, p_col, nE, owned);
    cudaEventRecord(evJoin, s2);

    // stream 0: Xd = fp16(X * deg)
    conv_deg<<<(nloc * 16 + 255) / 256, 256>>>(x, deg, p_xd, nloc * 16);

    // ---- join; gather first (needs CSR + Xd), then fused GEMMs ----
    cudaStreamWaitEvent(0, evJoin, 0);
    gather_agg<<<(owned * 32 + 255) / 256, 256>>>(p_xd, p_rs, p_col, p_agg, owned);
    gemm_fused<<<(owned + 127) / 128, 256>>>(p_agg, w1, b1, w2, deg, p_h2, owned);
    gather_out<<<(owned * 32 + 255) / 256, 256>>>(p_h2, p_rs, p_col, deg, b2, out, owned);
}